// round 16
// baseline (speedup 1.0000x reference)
#include <cuda_runtime.h>
#include <cuda_bf16.h>
#include <cstdint>

#define BB 256
#define NN 512
#define NP1 513
#define TT 33
#define DK 32
#define DIN 1024
#define DF 256
#define DTY 259
#define NG 128

#define LOGITS_ELEMS ((size_t)BB * TT * NP1)

// ---------------- scratch (device globals; no allocation allowed) ----------
__device__ float g_padkey[BB * NP1 * DK];   // keys + end row
__device__ float g_func[BB * DF];           // relu(mask_type @ Wfunc^T + b)
__device__ float g_pre10[BB * DF];          // emb0 @ Wfc1^T + b_fc1
__device__ float g_M[DF * DK];              // W_fc1 @ W_embed
__device__ float g_c1[DF];                  // W_fc1 @ b_embed
__device__ float g_wcomb[NG * DF];          // W_ih @ W_fc2
__device__ float g_gbias[NG];               // W_ih@b_fc2 + b_ih + b_hh
__device__ int   g_thr[BB * NP1];           // first-selected-step per (b,n)
__device__ float g_prefix[BB * TT * DK];    // exclusive prefix of selected keys / N
__device__ float g_relua[BB * TT * DF];     // relu(fc1 pre-activations)
__device__ float g_gx[BB * TT * NG];        // LSTM gate pre-activations
__device__ float g_h[BB * TT * 32];         // LSTM hidden per step

__device__ __forceinline__ float sigmoidf_(float x) {
    return 1.0f / (1.0f + __expf(-x));
}
__device__ __forceinline__ float dot4(float4 a, float4 b) {
    return fmaf(a.x, b.x, fmaf(a.y, b.y, fmaf(a.z, b.z, a.w * b.w)));
}

// pack2(lo, hi): bf16x2 with 'lo' in bits[15:0]
__device__ __forceinline__ uint32_t pack2(float lo, float hi) {
    uint32_t r;
    asm("cvt.rn.bf16x2.f32 %0, %1, %2;" : "=r"(r) : "f"(hi), "f"(lo));
    return r;
}
__device__ __forceinline__ void cvt_hilo(float x0, float x1, uint32_t& h, uint32_t& l) {
    h = pack2(x0, x1);
    float h0 = __uint_as_float(h << 16);
    float h1 = __uint_as_float(h & 0xffff0000u);
    l = pack2(x0 - h0, x1 - h1);
}
__device__ __forceinline__ void mma16816(float* d, uint32_t a0, uint32_t a1,
                                         uint32_t a2, uint32_t a3,
                                         uint32_t b0, uint32_t b1) {
    asm volatile(
        "mma.sync.aligned.m16n8k16.row.col.f32.bf16.bf16.f32 "
        "{%0,%1,%2,%3},{%4,%5,%6,%7},{%8,%9},{%0,%1,%2,%3};"
        : "+f"(d[0]), "+f"(d[1]), "+f"(d[2]), "+f"(d[3])
        : "r"(a0), "r"(a1), "r"(a2), "r"(a3), "r"(b0), "r"(b1));
}

// ================= generic fp32-in / fp32-out GEMM body (tensor cores) ======
// C[m,n] = sum_k A[m,k]*Bw[n,k] + bias[n]; optional relu; optional key remap.
template <int WARPS_M, int WARPS_N, int BK, bool KEYREMAP>
__device__ __forceinline__ void
gemm_body(const float* __restrict__ A, const float* __restrict__ Bw,
          float* __restrict__ C, const float* __restrict__ bias,
          int K, int ldc, bool relu, int m0, int n0) {
    constexpr int BM = WARPS_M * 16;
    constexpr int BN = WARPS_N * 32;
    constexpr int WPR = BK / 2;
    extern __shared__ uint32_t smem_u[];
    uint32_t* sAh = smem_u;
    uint32_t* sAl = sAh + BM * WPR;
    uint32_t* sBh = sAl + BM * WPR;
    uint32_t* sBl = sBh + BN * WPR;

    const int tid = threadIdx.x;
    const int wid = tid >> 5, lane = tid & 31;
    const int g = lane >> 2, tig = lane & 3;
    const int wm = wid % WARPS_M, wn = wid / WARPS_M;
    const bool k4 = ((K & 3) == 0);
    constexpr int NT = 256;

    float acc[4][4];
    for (int i = 0; i < 4; i++)
        for (int j = 0; j < 4; j++) acc[i][j] = 0.f;

    const int kiters = (K + BK - 1) / BK;
    for (int kt = 0; kt < kiters; kt++) {
        const int k0 = kt * BK;
        for (int idx = tid; idx < BM * (BK / 4); idx += NT) {
            int row = idx / (BK / 4), c4 = idx % (BK / 4);
            int gc = k0 + c4 * 4;
            float4 v = make_float4(0.f, 0.f, 0.f, 0.f);
            const float* ap = A + (size_t)(m0 + row) * K + gc;
            if (k4 && gc + 4 <= K) {
                v = *(const float4*)ap;
            } else {
                if (gc + 0 < K) v.x = ap[0];
                if (gc + 1 < K) v.y = ap[1];
                if (gc + 2 < K) v.z = ap[2];
                if (gc + 3 < K) v.w = ap[3];
            }
            uint32_t h0, l0, h1, l1;
            cvt_hilo(v.x, v.y, h0, l0);
            cvt_hilo(v.z, v.w, h1, l1);
            int w0 = (c4 * 2) ^ ((row & 7) << 2);
            *(uint2*)&sAh[row * WPR + w0] = make_uint2(h0, h1);
            *(uint2*)&sAl[row * WPR + w0] = make_uint2(l0, l1);
        }
        for (int idx = tid; idx < BN * (BK / 4); idx += NT) {
            int row = idx / (BK / 4), c4 = idx % (BK / 4);
            int gc = k0 + c4 * 4;
            float4 v = make_float4(0.f, 0.f, 0.f, 0.f);
            const float* bp = Bw + (size_t)(n0 + row) * K + gc;
            if (k4 && gc + 4 <= K) {
                v = *(const float4*)bp;
            } else {
                if (gc + 0 < K) v.x = bp[0];
                if (gc + 1 < K) v.y = bp[1];
                if (gc + 2 < K) v.z = bp[2];
                if (gc + 3 < K) v.w = bp[3];
            }
            uint32_t h0, l0, h1, l1;
            cvt_hilo(v.x, v.y, h0, l0);
            cvt_hilo(v.z, v.w, h1, l1);
            int w0 = (c4 * 2) ^ ((row & 7) << 2);
            *(uint2*)&sBh[row * WPR + w0] = make_uint2(h0, h1);
            *(uint2*)&sBl[row * WPR + w0] = make_uint2(l0, l1);
        }
        __syncthreads();
        const int sw = g << 2;
        const int ra0 = (wm * 16 + g) * WPR;
        const int ra1 = (wm * 16 + g + 8) * WPR;
#pragma unroll 4
        for (int c = 0; c < BK / 16; c++) {
            int ws0 = c * 8 + tig;
            uint32_t a0h = sAh[ra0 + (ws0 ^ sw)];
            uint32_t a1h = sAh[ra1 + (ws0 ^ sw)];
            uint32_t a2h = sAh[ra0 + ((ws0 + 4) ^ sw)];
            uint32_t a3h = sAh[ra1 + ((ws0 + 4) ^ sw)];
            uint32_t a0l = sAl[ra0 + (ws0 ^ sw)];
            uint32_t a1l = sAl[ra1 + (ws0 ^ sw)];
            uint32_t a2l = sAl[ra0 + ((ws0 + 4) ^ sw)];
            uint32_t a3l = sAl[ra1 + ((ws0 + 4) ^ sw)];
#pragma unroll
            for (int nt = 0; nt < 4; nt++) {
                int rb = (wn * 32 + nt * 8 + g) * WPR;
                uint32_t b0h = sBh[rb + (ws0 ^ sw)];
                uint32_t b1h = sBh[rb + ((ws0 + 4) ^ sw)];
                uint32_t b0l = sBl[rb + (ws0 ^ sw)];
                uint32_t b1l = sBl[rb + ((ws0 + 4) ^ sw)];
                mma16816(acc[nt], a0h, a1h, a2h, a3h, b0h, b1h);
                mma16816(acc[nt], a0h, a1h, a2h, a3h, b0l, b1l);
                mma16816(acc[nt], a0l, a1l, a2l, a3l, b0h, b1h);
            }
        }
        __syncthreads();
    }
#pragma unroll
    for (int nt = 0; nt < 4; nt++) {
        int col = n0 + wn * 32 + nt * 8 + 2 * tig;
        float b0v = __ldg(&bias[col]);
        float b1v = __ldg(&bias[col + 1]);
#pragma unroll
        for (int half = 0; half < 2; half++) {
            int r = m0 + wm * 16 + g + half * 8;
            int orow = KEYREMAP ? (r + (r >> 9)) : r;
            float x0 = acc[nt][half * 2 + 0] + b0v;
            float x1 = acc[nt][half * 2 + 1] + b1v;
            if (relu) { x0 = fmaxf(x0, 0.f); x1 = fmaxf(x1, 0.f); }
            *(float2*)&C[(size_t)orow * ldc + col] = make_float2(x0, x1);
        }
    }
}

// key GEMM wrapper: BK=128 -> 80KB smem -> 2 CTAs/SM
template <int WARPS_M, int WARPS_N, int BK, bool KEYREMAP>
__global__ void __launch_bounds__(256, 2)
gemm_k(const float* __restrict__ A, const float* __restrict__ Bw,
       float* __restrict__ C, const float* __restrict__ bias, int K, int ldc) {
    gemm_body<WARPS_M, WARPS_N, BK, KEYREMAP>(
        A, Bw, C, bias, K, ldc, false,
        blockIdx.x * WARPS_M * 16, blockIdx.y * WARPS_N * 32);
}
// gates GEMM wrapper (same config, no remap)
template <int WARPS_M, int WARPS_N, int BK>
__global__ void __launch_bounds__(256, 2)
gemm_g(const float* __restrict__ A, const float* __restrict__ Bw,
       float* __restrict__ C, const float* __restrict__ bias, int K, int ldc) {
    gemm_body<WARPS_M, WARPS_N, BK, false>(
        A, Bw, C, bias, K, ldc, false,
        blockIdx.x * WARPS_M * 16, blockIdx.y * WARPS_N * 32);
}
// dual small GEMM: z=0 -> pre10 (K=1024), z=1 -> func (K=259, relu)
__global__ void __launch_bounds__(256, 2)
gemm_dual(const float* A0, const float* B0, float* C0, const float* bias0, int K0,
          const float* A1, const float* B1, float* C1, const float* bias1, int K1) {
    if (blockIdx.z == 0)
        gemm_body<4, 2, 128, false>(A0, B0, C0, bias0, K0, 256, false,
                                    blockIdx.x * 64, blockIdx.y * 64);
    else
        gemm_body<4, 2, 128, false>(A1, B1, C1, bias1, K1, 256, true,
                                    blockIdx.x * 64, blockIdx.y * 64);
}

// ------- merged side precomputes: blocks 0..255 -> M/c1 row j; 256..383 -> wcomb
__global__ void k_side(const float* __restrict__ Wfc1,
                       const float* __restrict__ Wemb,
                       const float* __restrict__ bemb,
                       const float* __restrict__ Wfc2,
                       const float* __restrict__ bfc2,
                       const float* __restrict__ Wih,
                       const float* __restrict__ bih,
                       const float* __restrict__ bhh) {
    if (blockIdx.x < 256) {
        __shared__ float sred[8 * 32];
        __shared__ float sred1[8];
        int j = blockIdx.x;
        int lane = threadIdx.x & 31, w = threadIdx.x >> 5;
        const float* arow = Wfc1 + (size_t)j * 1024 + w * 128;
        float acc = 0.f;
#pragma unroll 8
        for (int i = 0; i < 128; i++) {
            float a = __ldg(&arow[i]);
            acc = fmaf(a, __ldg(&Wemb[(size_t)(w * 128 + i) * 32 + lane]), acc);
        }
        float a1 = 0.f;
#pragma unroll
        for (int q = 0; q < 4; q++) {
            int i = q * 32 + lane;
            a1 = fmaf(__ldg(&arow[i]), __ldg(&bemb[w * 128 + i]), a1);
        }
#pragma unroll
        for (int off = 16; off > 0; off >>= 1)
            a1 += __shfl_xor_sync(0xffffffffu, a1, off);
        if (lane == 0) sred1[w] = a1;
        sred[w * 32 + lane] = acc;
        __syncthreads();
        if (threadIdx.x < 32) {
            float s = 0.f;
#pragma unroll
            for (int gp = 0; gp < 8; gp++) s += sred[gp * 32 + threadIdx.x];
            g_M[j * 32 + threadIdx.x] = s;
            if (threadIdx.x == 0) {
                float s1 = 0.f;
#pragma unroll
                for (int gp = 0; gp < 8; gp++) s1 += sred1[gp];
                g_c1[j] = s1;
            }
        }
    } else {
        __shared__ float sWih[32];
        int gi = blockIdx.x - 256;
        int tid = threadIdx.x;
        if (tid < 32) sWih[tid] = Wih[gi * 32 + tid];
        __syncthreads();
        float acc = 0.f;
#pragma unroll
        for (int k = 0; k < 32; k++)
            acc = fmaf(sWih[k], __ldg(&Wfc2[k * 256 + tid]), acc);
        g_wcomb[gi * 256 + tid] = acc;
        if (tid == 0) {
            float b = bih[gi] + bhh[gi];
#pragma unroll
            for (int k = 0; k < 32; k++) b = fmaf(sWih[k], bfc2[k], b);
            g_gbias[gi] = b;
        }
    }
}

// -------- availability thresholds + selected-key prefix sums + end rows ----
__global__ void k_prep(const float* __restrict__ avail,
                       const int* __restrict__ selected,
                       const float* __restrict__ endv) {
    __shared__ int s_thr[NP1];
    int b = blockIdx.x;
    int lane = threadIdx.x;  // 32 threads
    g_padkey[((size_t)b * NP1 + 512) * 32 + lane] = endv[lane];
    for (int n = lane; n < NP1; n += 32)
        s_thr[n] = (n == 512) ? 33 : (avail[(size_t)b * 512 + n] > 0.5f ? 33 : -1);
    __syncwarp();
    int selv = selected[b * 32 + lane];
    float rr[32];
#pragma unroll
    for (int t = 0; t < 32; t++) {
        int s = __shfl_sync(0xffffffffu, selv, t);
        rr[t] = __ldg(&g_padkey[((size_t)b * NP1 + s) * 32 + lane]);
    }
    float acc = 0.f;
    const float inv_n = 1.0f / 512.0f;
#pragma unroll
    for (int t = 0; t < 32; t++) {
        g_prefix[((size_t)b * TT + t) * 32 + lane] = acc;
        acc = fmaf(rr[t], inv_n, acc);
        int s = __shfl_sync(0xffffffffu, selv, t);
        if (lane == 0) {
            int v = s_thr[s];
            if (v < 0 || v >= 32) s_thr[s] = t;
        }
    }
    __syncwarp();
    g_prefix[((size_t)b * TT + 32) * 32 + lane] = acc;
    for (int n = lane; n < NP1; n += 32)
        g_thr[(size_t)b * NP1 + n] = s_thr[n];
}

// -------- relu_a[b,t,:] = relu(pre10 + func + t*c1 + prefix_t @ M^T) --------
__global__ void k_gA() {
    __shared__ float sp[TT * 32];
    int b = blockIdx.x, tid = threadIdx.x;
    for (int i = tid; i < TT * 32; i += 256) sp[i] = g_prefix[(size_t)b * TT * 32 + i];
    float pre = g_pre10[(size_t)b * 256 + tid] + g_func[(size_t)b * 256 + tid];
    float c1 = g_c1[tid];
    float m[32];
    const float4* mr = reinterpret_cast<const float4*>(g_M + tid * 32);
#pragma unroll
    for (int q = 0; q < 8; q++) {
        float4 v = __ldg(mr + q);
        m[q * 4 + 0] = v.x; m[q * 4 + 1] = v.y; m[q * 4 + 2] = v.z; m[q * 4 + 3] = v.w;
    }
    __syncthreads();
    for (int t = 0; t < TT; t++) {
        float acc = fmaf((float)t, c1, pre);
        const float* p = &sp[t * 32];
#pragma unroll
        for (int k = 0; k < 32; k++) acc = fmaf(m[k], p[k], acc);
        g_relua[((size_t)b * TT + t) * 256 + tid] = fmaxf(acc, 0.f);
    }
}

// ---------------- LSTM recurrence -----------
__global__ void k_lstm(const float* __restrict__ Whh) {
    __shared__ float sW[128 * 33];
    __shared__ float s_h[32];
    __shared__ float s_c[32];
    __shared__ float s_g[128];
    int b = blockIdx.x, tid = threadIdx.x;
    for (int idx = tid; idx < 128 * 32; idx += 128) {
        int gg2 = idx >> 5, kk = idx & 31;
        sW[gg2 * 33 + kk] = Whh[idx];
    }
    if (tid < 32) { s_h[tid] = 0.f; s_c[tid] = 0.f; }
    __syncthreads();
    for (int t = 0; t < TT; t++) {
        float gg = g_gx[((size_t)b * TT + t) * 128 + tid];
        const float* wrow = &sW[tid * 33];
#pragma unroll
        for (int kk = 0; kk < 32; kk++) gg = fmaf(wrow[kk], s_h[kk], gg);
        s_g[tid] = gg;
        __syncthreads();
        if (tid < 32) {
            float ig = sigmoidf_(s_g[tid]);
            float fg = sigmoidf_(s_g[32 + tid]);
            float gt = tanhf(s_g[64 + tid]);
            float og = sigmoidf_(s_g[96 + tid]);
            float c = fmaf(fg, s_c[tid], ig * gt);
            float h = og * tanhf(c);
            s_c[tid] = c;
            s_h[tid] = h;
            g_h[((size_t)b * TT + t) * 32 + tid] = h;
        }
        __syncthreads();
    }
}

// ---------------- logits[b,t,n] = h_t . key_n - mask --------------------
__global__ void k_logits(float* __restrict__ out) {
    __shared__ float s_h[TT * 32];
    __shared__ float s_key[128 * 36];
    int b = blockIdx.y, n0 = blockIdx.x * 128, tid = threadIdx.x;
    for (int idx = tid; idx < TT * 32; idx += 256)
        s_h[idx] = g_h[(size_t)b * (TT * 32) + idx];
    int nmax = NP1 - n0; if (nmax > 128) nmax = 128;
    for (int idx = tid; idx < nmax * 32; idx += 256) {
        int r = idx >> 5, kk = idx & 31;
        s_key[r * 36 + kk] = g_padkey[((size_t)(b * NP1 + n0)) * 32 + idx];
    }
    __syncthreads();
    int nn = tid & 127, ts = tid >> 7;
    if (nn < nmax) {
        int n = n0 + nn;
        float4 kr[8];
        const float4* k4 = reinterpret_cast<const float4*>(&s_key[nn * 36]);
#pragma unroll
        for (int q = 0; q < 8; q++) kr[q] = k4[q];
        int thr = g_thr[(size_t)b * NP1 + n];
        for (int t = ts; t < TT; t += 2) {
            const float4* h4 = reinterpret_cast<const float4*>(&s_h[t * 32]);
            float acc = 0.f;
#pragma unroll
            for (int q = 0; q < 8; q++) acc += dot4(h4[q], kr[q]);
            out[((size_t)b * TT + t) * NP1 + n] = acc - (t > thr ? 1e9f : 0.f);
        }
    }
}

// ---------------- final emb output ---------------------------------------
__global__ void k_emb(float* __restrict__ out,
                      const float* __restrict__ emb0,
                      const float* __restrict__ Wemb,
                      const float* __restrict__ bemb) {
    __shared__ float s_p[32];
    int b = blockIdx.x, tid = threadIdx.x;
    if (tid < 32) s_p[tid] = g_prefix[((size_t)b * TT + 32) * 32 + tid];
    __syncthreads();
    const float4* p4 = reinterpret_cast<const float4*>(s_p);
#pragma unroll
    for (int q = 0; q < 4; q++) {
        int i = q * 256 + tid;
        const float4* we = reinterpret_cast<const float4*>(Wemb + (size_t)i * 32);
        float acc = __ldg(&emb0[(size_t)b * 1024 + i]) + 32.0f * __ldg(&bemb[i]);
#pragma unroll
        for (int r = 0; r < 8; r++) acc += dot4(__ldg(we + r), p4[r]);
        out[LOGITS_ELEMS + (size_t)b * 1024 + i] = acc;
    }
}

// ---------------- launch -----------------------------------------------------
extern "C" void kernel_launch(void* const* d_in, const int* in_sizes, int n_in,
                              void* d_out, int out_size) {
    const float* embedding = (const float*)d_in[0];
    const float* type_mask = (const float*)d_in[1];
    const float* avail     = (const float*)d_in[2];
    const float* ent       = (const float*)d_in[3];
    const int*   selected  = (const int*)d_in[4];
    const float* endv      = (const float*)d_in[5];
    const float* W_key  = (const float*)d_in[6];
    const float* b_key  = (const float*)d_in[7];
    const float* W_func = (const float*)d_in[8];
    const float* b_func = (const float*)d_in[9];
    const float* W_fc1  = (const float*)d_in[10];
    const float* b_fc1  = (const float*)d_in[11];
    const float* W_fc2  = (const float*)d_in[12];
    const float* b_fc2  = (const float*)d_in[13];
    const float* W_emb  = (const float*)d_in[14];
    const float* b_emb  = (const float*)d_in[15];
    const float* W_ih   = (const float*)d_in[16];
    const float* b_ih   = (const float*)d_in[17];
    const float* W_hh   = (const float*)d_in[18];
    const float* b_hh   = (const float*)d_in[19];
    float* out = (float*)d_out;

    // smem: (8,1,128): 2*(128+32)*64*4 = 81920 B -> 2 CTAs/SM
    //       (4,2,128): 2*(64+64)*64*4  = 65536 B
    const int SMB = 81920, SM2 = 65536;
    cudaFuncSetAttribute(gemm_k<8, 1, 128, true>,
                         cudaFuncAttributeMaxDynamicSharedMemorySize, SMB);
    cudaFuncSetAttribute(gemm_g<8, 1, 128>,
                         cudaFuncAttributeMaxDynamicSharedMemorySize, SMB);
    cudaFuncSetAttribute(gemm_dual,
                         cudaFuncAttributeMaxDynamicSharedMemorySize, SM2);

    float* padkey; cudaGetSymbolAddress((void**)&padkey, g_padkey);
    float* pre10;  cudaGetSymbolAddress((void**)&pre10, g_pre10);
    float* funcb;  cudaGetSymbolAddress((void**)&funcb, g_func);
    float* relua;  cudaGetSymbolAddress((void**)&relua, g_relua);
    float* gx;     cudaGetSymbolAddress((void**)&gx, g_gx);
    float* wcomb;  cudaGetSymbolAddress((void**)&wcomb, g_wcomb);
    float* gbias;  cudaGetSymbolAddress((void**)&gbias, g_gbias);

    cudaStream_t s1;
    cudaStreamCreateWithFlags(&s1, cudaStreamNonBlocking);
    cudaEvent_t evFork, evS1, evPrep, evEmb;
    cudaEventCreateWithFlags(&evFork, cudaEventDisableTiming);
    cudaEventCreateWithFlags(&evS1, cudaEventDisableTiming);
    cudaEventCreateWithFlags(&evPrep, cudaEventDisableTiming);
    cudaEventCreateWithFlags(&evEmb, cudaEventDisableTiming);

    // ---- fork: side branch (independent of the big key GEMM) ----
    cudaEventRecord(evFork, 0);
    cudaStreamWaitEvent(s1, evFork, 0);
    gemm_dual<<<dim3(4, 4, 2), 256, SM2, s1>>>(
        embedding, W_fc1, pre10, b_fc1, 1024,
        type_mask, W_func, funcb, b_func, DTY);
    k_side<<<384, 256, 0, s1>>>(W_fc1, W_emb, b_emb, W_fc2, b_fc2, W_ih, b_ih, b_hh);
    cudaEventRecord(evS1, s1);

    // ---- main stream: key GEMM -> prep ----
    gemm_k<8, 1, 128, true>
        <<<dim3(BB * NN / 128, 1), 256, SMB>>>(ent, W_key, padkey, b_key, 256, 32);
    k_prep<<<BB, 32>>>(avail, selected, endv);
    cudaEventRecord(evPrep, 0);

    // ---- k_emb only needs g_prefix: run on side stream ----
    cudaStreamWaitEvent(s1, evPrep, 0);
    k_emb<<<BB, 256, 0, s1>>>(out, embedding, W_emb, b_emb);
    cudaEventRecord(evEmb, s1);

    // ---- main chain continues after side precomputes land ----
    cudaStreamWaitEvent(0, evS1, 0);
    k_gA<<<BB, 256>>>();
    gemm_g<8, 1, 128>
        <<<dim3(BB * TT / 128, 4), 256, SMB>>>(relua, wcomb, gx, gbias, 256, 128);
    k_lstm<<<BB, 128>>>(W_hh);
    k_logits<<<dim3(5, BB), 256>>>(out);

    // ---- join ----
    cudaStreamWaitEvent(0, evEmb, 0);
}

// round 17
// speedup vs baseline: 1.0093x; 1.0093x over previous
#include <cuda_runtime.h>
#include <cuda_bf16.h>
#include <cstdint>

#define BB 256
#define NN 512
#define NP1 513
#define TT 33
#define DK 32
#define DIN 1024
#define DF 256
#define DTY 259
#define NG 128

#define LOGITS_ELEMS ((size_t)BB * TT * NP1)

// ---------------- scratch (device globals; no allocation allowed) ----------
__device__ float g_padkey[BB * NP1 * DK];   // keys + end row
__device__ float g_func[BB * DF];           // relu(mask_type @ Wfunc^T + b)
__device__ float g_pre10[BB * DF];          // emb0 @ Wfc1^T + b_fc1
__device__ float g_M[DF * DK];              // W_fc1 @ W_embed
__device__ float g_c1[DF];                  // W_fc1 @ b_embed
__device__ float g_wcomb[NG * DF];          // W_ih @ W_fc2
__device__ float g_gbias[NG];               // W_ih@b_fc2 + b_ih + b_hh
__device__ int   g_thr[BB * NP1];           // first-selected-step per (b,n)
__device__ float g_prefix[BB * TT * DK];    // exclusive prefix of selected keys / N
__device__ float g_relua[BB * TT * DF];     // relu(fc1 pre-activations)
__device__ float g_gx[BB * TT * NG];        // LSTM gate pre-activations
__device__ float g_h[BB * TT * 32];         // LSTM hidden per step

__device__ __forceinline__ float sigmoidf_(float x) {
    return 1.0f / (1.0f + __expf(-x));
}
__device__ __forceinline__ float dot4(float4 a, float4 b) {
    return fmaf(a.x, b.x, fmaf(a.y, b.y, fmaf(a.z, b.z, a.w * b.w)));
}

// pack2(lo, hi): bf16x2 with 'lo' in bits[15:0]
__device__ __forceinline__ uint32_t pack2(float lo, float hi) {
    uint32_t r;
    asm("cvt.rn.bf16x2.f32 %0, %1, %2;" : "=r"(r) : "f"(hi), "f"(lo));
    return r;
}
__device__ __forceinline__ void cvt_hilo(float x0, float x1, uint32_t& h, uint32_t& l) {
    h = pack2(x0, x1);
    float h0 = __uint_as_float(h << 16);
    float h1 = __uint_as_float(h & 0xffff0000u);
    l = pack2(x0 - h0, x1 - h1);
}
__device__ __forceinline__ void mma16816(float* d, uint32_t a0, uint32_t a1,
                                         uint32_t a2, uint32_t a3,
                                         uint32_t b0, uint32_t b1) {
    asm volatile(
        "mma.sync.aligned.m16n8k16.row.col.f32.bf16.bf16.f32 "
        "{%0,%1,%2,%3},{%4,%5,%6,%7},{%8,%9},{%0,%1,%2,%3};"
        : "+f"(d[0]), "+f"(d[1]), "+f"(d[2]), "+f"(d[3])
        : "r"(a0), "r"(a1), "r"(a2), "r"(a3), "r"(b0), "r"(b1));
}

// ================= generic fp32-in / fp32-out GEMM body (tensor cores) ======
// C[m,n] = sum_k A[m,k]*Bw[n,k] + bias[n]; optional relu; optional key remap.
template <int WARPS_M, int WARPS_N, int BK, bool KEYREMAP>
__device__ __forceinline__ void
gemm_body(const float* __restrict__ A, const float* __restrict__ Bw,
          float* __restrict__ C, const float* __restrict__ bias,
          int K, int ldc, bool relu, int m0, int n0) {
    constexpr int BM = WARPS_M * 16;
    constexpr int BN = WARPS_N * 32;
    constexpr int WPR = BK / 2;
    extern __shared__ uint32_t smem_u[];
    uint32_t* sAh = smem_u;
    uint32_t* sAl = sAh + BM * WPR;
    uint32_t* sBh = sAl + BM * WPR;
    uint32_t* sBl = sBh + BN * WPR;

    const int tid = threadIdx.x;
    const int wid = tid >> 5, lane = tid & 31;
    const int g = lane >> 2, tig = lane & 3;
    const int wm = wid % WARPS_M, wn = wid / WARPS_M;
    const bool k4 = ((K & 3) == 0);
    constexpr int NT = 256;

    float acc[4][4];
    for (int i = 0; i < 4; i++)
        for (int j = 0; j < 4; j++) acc[i][j] = 0.f;

    const int kiters = (K + BK - 1) / BK;
    for (int kt = 0; kt < kiters; kt++) {
        const int k0 = kt * BK;
        for (int idx = tid; idx < BM * (BK / 4); idx += NT) {
            int row = idx / (BK / 4), c4 = idx % (BK / 4);
            int gc = k0 + c4 * 4;
            float4 v = make_float4(0.f, 0.f, 0.f, 0.f);
            const float* ap = A + (size_t)(m0 + row) * K + gc;
            if (k4 && gc + 4 <= K) {
                v = *(const float4*)ap;
            } else {
                if (gc + 0 < K) v.x = ap[0];
                if (gc + 1 < K) v.y = ap[1];
                if (gc + 2 < K) v.z = ap[2];
                if (gc + 3 < K) v.w = ap[3];
            }
            uint32_t h0, l0, h1, l1;
            cvt_hilo(v.x, v.y, h0, l0);
            cvt_hilo(v.z, v.w, h1, l1);
            int w0 = (c4 * 2) ^ ((row & 7) << 2);
            *(uint2*)&sAh[row * WPR + w0] = make_uint2(h0, h1);
            *(uint2*)&sAl[row * WPR + w0] = make_uint2(l0, l1);
        }
        for (int idx = tid; idx < BN * (BK / 4); idx += NT) {
            int row = idx / (BK / 4), c4 = idx % (BK / 4);
            int gc = k0 + c4 * 4;
            float4 v = make_float4(0.f, 0.f, 0.f, 0.f);
            const float* bp = Bw + (size_t)(n0 + row) * K + gc;
            if (k4 && gc + 4 <= K) {
                v = *(const float4*)bp;
            } else {
                if (gc + 0 < K) v.x = bp[0];
                if (gc + 1 < K) v.y = bp[1];
                if (gc + 2 < K) v.z = bp[2];
                if (gc + 3 < K) v.w = bp[3];
            }
            uint32_t h0, l0, h1, l1;
            cvt_hilo(v.x, v.y, h0, l0);
            cvt_hilo(v.z, v.w, h1, l1);
            int w0 = (c4 * 2) ^ ((row & 7) << 2);
            *(uint2*)&sBh[row * WPR + w0] = make_uint2(h0, h1);
            *(uint2*)&sBl[row * WPR + w0] = make_uint2(l0, l1);
        }
        __syncthreads();
        const int sw = g << 2;
        const int ra0 = (wm * 16 + g) * WPR;
        const int ra1 = (wm * 16 + g + 8) * WPR;
#pragma unroll 4
        for (int c = 0; c < BK / 16; c++) {
            int ws0 = c * 8 + tig;
            uint32_t a0h = sAh[ra0 + (ws0 ^ sw)];
            uint32_t a1h = sAh[ra1 + (ws0 ^ sw)];
            uint32_t a2h = sAh[ra0 + ((ws0 + 4) ^ sw)];
            uint32_t a3h = sAh[ra1 + ((ws0 + 4) ^ sw)];
            uint32_t a0l = sAl[ra0 + (ws0 ^ sw)];
            uint32_t a1l = sAl[ra1 + (ws0 ^ sw)];
            uint32_t a2l = sAl[ra0 + ((ws0 + 4) ^ sw)];
            uint32_t a3l = sAl[ra1 + ((ws0 + 4) ^ sw)];
#pragma unroll
            for (int nt = 0; nt < 4; nt++) {
                int rb = (wn * 32 + nt * 8 + g) * WPR;
                uint32_t b0h = sBh[rb + (ws0 ^ sw)];
                uint32_t b1h = sBh[rb + ((ws0 + 4) ^ sw)];
                uint32_t b0l = sBl[rb + (ws0 ^ sw)];
                uint32_t b1l = sBl[rb + ((ws0 + 4) ^ sw)];
                mma16816(acc[nt], a0h, a1h, a2h, a3h, b0h, b1h);
                mma16816(acc[nt], a0h, a1h, a2h, a3h, b0l, b1l);
                mma16816(acc[nt], a0l, a1l, a2l, a3l, b0h, b1h);
            }
        }
        __syncthreads();
    }
#pragma unroll
    for (int nt = 0; nt < 4; nt++) {
        int col = n0 + wn * 32 + nt * 8 + 2 * tig;
        float b0v = __ldg(&bias[col]);
        float b1v = __ldg(&bias[col + 1]);
#pragma unroll
        for (int half = 0; half < 2; half++) {
            int r = m0 + wm * 16 + g + half * 8;
            int orow = KEYREMAP ? (r + (r >> 9)) : r;
            float x0 = acc[nt][half * 2 + 0] + b0v;
            float x1 = acc[nt][half * 2 + 1] + b1v;
            if (relu) { x0 = fmaxf(x0, 0.f); x1 = fmaxf(x1, 0.f); }
            *(float2*)&C[(size_t)orow * ldc + col] = make_float2(x0, x1);
        }
    }
}

// key GEMM wrapper: BK=128 -> 80KB smem -> 2 CTAs/SM
template <int WARPS_M, int WARPS_N, int BK, bool KEYREMAP>
__global__ void __launch_bounds__(256, 2)
gemm_k(const float* __restrict__ A, const float* __restrict__ Bw,
       float* __restrict__ C, const float* __restrict__ bias, int K, int ldc) {
    gemm_body<WARPS_M, WARPS_N, BK, KEYREMAP>(
        A, Bw, C, bias, K, ldc, false,
        blockIdx.x * WARPS_M * 16, blockIdx.y * WARPS_N * 32);
}
// gates GEMM wrapper (same config, no remap)
template <int WARPS_M, int WARPS_N, int BK>
__global__ void __launch_bounds__(256, 2)
gemm_g(const float* __restrict__ A, const float* __restrict__ Bw,
       float* __restrict__ C, const float* __restrict__ bias, int K, int ldc) {
    gemm_body<WARPS_M, WARPS_N, BK, false>(
        A, Bw, C, bias, K, ldc, false,
        blockIdx.x * WARPS_M * 16, blockIdx.y * WARPS_N * 32);
}
// dual small GEMM: z=0 -> pre10 (K=1024), z=1 -> func (K=259, relu)
__global__ void __launch_bounds__(256, 2)
gemm_dual(const float* A0, const float* B0, float* C0, const float* bias0, int K0,
          const float* A1, const float* B1, float* C1, const float* bias1, int K1) {
    if (blockIdx.z == 0)
        gemm_body<4, 2, 128, false>(A0, B0, C0, bias0, K0, 256, false,
                                    blockIdx.x * 64, blockIdx.y * 64);
    else
        gemm_body<4, 2, 128, false>(A1, B1, C1, bias1, K1, 256, true,
                                    blockIdx.x * 64, blockIdx.y * 64);
}

// ------- merged side precomputes: blocks 0..255 -> M/c1 row j; 256..383 -> wcomb
__global__ void k_side(const float* __restrict__ Wfc1,
                       const float* __restrict__ Wemb,
                       const float* __restrict__ bemb,
                       const float* __restrict__ Wfc2,
                       const float* __restrict__ bfc2,
                       const float* __restrict__ Wih,
                       const float* __restrict__ bih,
                       const float* __restrict__ bhh) {
    if (blockIdx.x < 256) {
        __shared__ float sred[8 * 32];
        __shared__ float sred1[8];
        int j = blockIdx.x;
        int lane = threadIdx.x & 31, w = threadIdx.x >> 5;
        const float* arow = Wfc1 + (size_t)j * 1024 + w * 128;
        float acc = 0.f;
#pragma unroll 8
        for (int i = 0; i < 128; i++) {
            float a = __ldg(&arow[i]);
            acc = fmaf(a, __ldg(&Wemb[(size_t)(w * 128 + i) * 32 + lane]), acc);
        }
        float a1 = 0.f;
#pragma unroll
        for (int q = 0; q < 4; q++) {
            int i = q * 32 + lane;
            a1 = fmaf(__ldg(&arow[i]), __ldg(&bemb[w * 128 + i]), a1);
        }
#pragma unroll
        for (int off = 16; off > 0; off >>= 1)
            a1 += __shfl_xor_sync(0xffffffffu, a1, off);
        if (lane == 0) sred1[w] = a1;
        sred[w * 32 + lane] = acc;
        __syncthreads();
        if (threadIdx.x < 32) {
            float s = 0.f;
#pragma unroll
            for (int gp = 0; gp < 8; gp++) s += sred[gp * 32 + threadIdx.x];
            g_M[j * 32 + threadIdx.x] = s;
            if (threadIdx.x == 0) {
                float s1 = 0.f;
#pragma unroll
                for (int gp = 0; gp < 8; gp++) s1 += sred1[gp];
                g_c1[j] = s1;
            }
        }
    } else {
        __shared__ float sWih[32];
        int gi = blockIdx.x - 256;
        int tid = threadIdx.x;
        if (tid < 32) sWih[tid] = Wih[gi * 32 + tid];
        __syncthreads();
        float acc = 0.f;
#pragma unroll
        for (int k = 0; k < 32; k++)
            acc = fmaf(sWih[k], __ldg(&Wfc2[k * 256 + tid]), acc);
        g_wcomb[gi * 256 + tid] = acc;
        if (tid == 0) {
            float b = bih[gi] + bhh[gi];
#pragma unroll
            for (int k = 0; k < 32; k++) b = fmaf(sWih[k], bfc2[k], b);
            g_gbias[gi] = b;
        }
    }
}

// -------- availability thresholds + selected-key prefix sums + end rows ----
__global__ void k_prep(const float* __restrict__ avail,
                       const int* __restrict__ selected,
                       const float* __restrict__ endv) {
    __shared__ int s_thr[NP1];
    int b = blockIdx.x;
    int lane = threadIdx.x;  // 32 threads
    g_padkey[((size_t)b * NP1 + 512) * 32 + lane] = endv[lane];
    for (int n = lane; n < NP1; n += 32)
        s_thr[n] = (n == 512) ? 33 : (avail[(size_t)b * 512 + n] > 0.5f ? 33 : -1);
    __syncwarp();
    int selv = selected[b * 32 + lane];
    float rr[32];
#pragma unroll
    for (int t = 0; t < 32; t++) {
        int s = __shfl_sync(0xffffffffu, selv, t);
        rr[t] = __ldg(&g_padkey[((size_t)b * NP1 + s) * 32 + lane]);
    }
    float acc = 0.f;
    const float inv_n = 1.0f / 512.0f;
#pragma unroll
    for (int t = 0; t < 32; t++) {
        g_prefix[((size_t)b * TT + t) * 32 + lane] = acc;
        acc = fmaf(rr[t], inv_n, acc);
        int s = __shfl_sync(0xffffffffu, selv, t);
        if (lane == 0) {
            int v = s_thr[s];
            if (v < 0 || v >= 32) s_thr[s] = t;
        }
    }
    __syncwarp();
    g_prefix[((size_t)b * TT + 32) * 32 + lane] = acc;
    for (int n = lane; n < NP1; n += 32)
        g_thr[(size_t)b * NP1 + n] = s_thr[n];
}

// -------- relu_a[b,t,:] = relu(pre10 + func + t*c1 + prefix_t @ M^T) --------
__global__ void k_gA() {
    __shared__ float sp[TT * 32];
    int b = blockIdx.x, tid = threadIdx.x;
    for (int i = tid; i < TT * 32; i += 256) sp[i] = g_prefix[(size_t)b * TT * 32 + i];
    float pre = g_pre10[(size_t)b * 256 + tid] + g_func[(size_t)b * 256 + tid];
    float c1 = g_c1[tid];
    float m[32];
    const float4* mr = reinterpret_cast<const float4*>(g_M + tid * 32);
#pragma unroll
    for (int q = 0; q < 8; q++) {
        float4 v = __ldg(mr + q);
        m[q * 4 + 0] = v.x; m[q * 4 + 1] = v.y; m[q * 4 + 2] = v.z; m[q * 4 + 3] = v.w;
    }
    __syncthreads();
    for (int t = 0; t < TT; t++) {
        float acc = fmaf((float)t, c1, pre);
        const float* p = &sp[t * 32];
#pragma unroll
        for (int k = 0; k < 32; k++) acc = fmaf(m[k], p[k], acc);
        g_relua[((size_t)b * TT + t) * 256 + tid] = fmaxf(acc, 0.f);
    }
}

// ---------------- LSTM recurrence -----------
__global__ void k_lstm(const float* __restrict__ Whh) {
    __shared__ float sW[128 * 33];
    __shared__ float s_h[32];
    __shared__ float s_c[32];
    __shared__ float s_g[128];
    int b = blockIdx.x, tid = threadIdx.x;
    for (int idx = tid; idx < 128 * 32; idx += 128) {
        int gg2 = idx >> 5, kk = idx & 31;
        sW[gg2 * 33 + kk] = Whh[idx];
    }
    if (tid < 32) { s_h[tid] = 0.f; s_c[tid] = 0.f; }
    __syncthreads();
    for (int t = 0; t < TT; t++) {
        float gg = g_gx[((size_t)b * TT + t) * 128 + tid];
        const float* wrow = &sW[tid * 33];
#pragma unroll
        for (int kk = 0; kk < 32; kk++) gg = fmaf(wrow[kk], s_h[kk], gg);
        s_g[tid] = gg;
        __syncthreads();
        if (tid < 32) {
            float ig = sigmoidf_(s_g[tid]);
            float fg = sigmoidf_(s_g[32 + tid]);
            float gt = tanhf(s_g[64 + tid]);
            float og = sigmoidf_(s_g[96 + tid]);
            float c = fmaf(fg, s_c[tid], ig * gt);
            float h = og * tanhf(c);
            s_c[tid] = c;
            s_h[tid] = h;
            g_h[((size_t)b * TT + t) * 32 + tid] = h;
        }
        __syncthreads();
    }
}

// ---------------- logits[b,t,n] = h_t . key_n - mask --------------------
__global__ void k_logits(float* __restrict__ out) {
    __shared__ float s_h[TT * 32];
    __shared__ float s_key[128 * 36];
    int b = blockIdx.y, n0 = blockIdx.x * 128, tid = threadIdx.x;
    for (int idx = tid; idx < TT * 32; idx += 256)
        s_h[idx] = g_h[(size_t)b * (TT * 32) + idx];
    int nmax = NP1 - n0; if (nmax > 128) nmax = 128;
    for (int idx = tid; idx < nmax * 32; idx += 256) {
        int r = idx >> 5, kk = idx & 31;
        s_key[r * 36 + kk] = g_padkey[((size_t)(b * NP1 + n0)) * 32 + idx];
    }
    __syncthreads();
    int nn = tid & 127, ts = tid >> 7;
    if (nn < nmax) {
        int n = n0 + nn;
        float4 kr[8];
        const float4* k4 = reinterpret_cast<const float4*>(&s_key[nn * 36]);
#pragma unroll
        for (int q = 0; q < 8; q++) kr[q] = k4[q];
        int thr = g_thr[(size_t)b * NP1 + n];
        for (int t = ts; t < TT; t += 2) {
            const float4* h4 = reinterpret_cast<const float4*>(&s_h[t * 32]);
            float acc = 0.f;
#pragma unroll
            for (int q = 0; q < 8; q++) acc += dot4(h4[q], kr[q]);
            out[((size_t)b * TT + t) * NP1 + n] = acc - (t > thr ? 1e9f : 0.f);
        }
    }
}

// ---------------- final emb output ---------------------------------------
__global__ void k_emb(float* __restrict__ out,
                      const float* __restrict__ emb0,
                      const float* __restrict__ Wemb,
                      const float* __restrict__ bemb) {
    __shared__ float s_p[32];
    int b = blockIdx.x, tid = threadIdx.x;
    if (tid < 32) s_p[tid] = g_prefix[((size_t)b * TT + 32) * 32 + tid];
    __syncthreads();
    const float4* p4 = reinterpret_cast<const float4*>(s_p);
#pragma unroll
    for (int q = 0; q < 4; q++) {
        int i = q * 256 + tid;
        const float4* we = reinterpret_cast<const float4*>(Wemb + (size_t)i * 32);
        float acc = __ldg(&emb0[(size_t)b * 1024 + i]) + 32.0f * __ldg(&bemb[i]);
#pragma unroll
        for (int r = 0; r < 8; r++) acc += dot4(__ldg(we + r), p4[r]);
        out[LOGITS_ELEMS + (size_t)b * 1024 + i] = acc;
    }
}

// ---------------- launch -----------------------------------------------------
extern "C" void kernel_launch(void* const* d_in, const int* in_sizes, int n_in,
                              void* d_out, int out_size) {
    const float* embedding = (const float*)d_in[0];
    const float* type_mask = (const float*)d_in[1];
    const float* avail     = (const float*)d_in[2];
    const float* ent       = (const float*)d_in[3];
    const int*   selected  = (const int*)d_in[4];
    const float* endv      = (const float*)d_in[5];
    const float* W_key  = (const float*)d_in[6];
    const float* b_key  = (const float*)d_in[7];
    const float* W_func = (const float*)d_in[8];
    const float* b_func = (const float*)d_in[9];
    const float* W_fc1  = (const float*)d_in[10];
    const float* b_fc1  = (const float*)d_in[11];
    const float* W_fc2  = (const float*)d_in[12];
    const float* b_fc2  = (const float*)d_in[13];
    const float* W_emb  = (const float*)d_in[14];
    const float* b_emb  = (const float*)d_in[15];
    const float* W_ih   = (const float*)d_in[16];
    const float* b_ih   = (const float*)d_in[17];
    const float* W_hh   = (const float*)d_in[18];
    const float* b_hh   = (const float*)d_in[19];
    float* out = (float*)d_out;

    // smem: (8,1,128): 2*(128+32)*64*4 = 81920 B -> 2 CTAs/SM
    //       (4,2,128): 2*(64+64)*64*4  = 65536 B
    const int SMB = 81920, SM2 = 65536;
    cudaFuncSetAttribute(gemm_k<8, 1, 128, true>,
                         cudaFuncAttributeMaxDynamicSharedMemorySize, SMB);
    cudaFuncSetAttribute(gemm_g<8, 1, 128>,
                         cudaFuncAttributeMaxDynamicSharedMemorySize, SMB);
    cudaFuncSetAttribute(gemm_dual,
                         cudaFuncAttributeMaxDynamicSharedMemorySize, SM2);

    float* padkey; cudaGetSymbolAddress((void**)&padkey, g_padkey);
    float* pre10;  cudaGetSymbolAddress((void**)&pre10, g_pre10);
    float* funcb;  cudaGetSymbolAddress((void**)&funcb, g_func);
    float* relua;  cudaGetSymbolAddress((void**)&relua, g_relua);
    float* gx;     cudaGetSymbolAddress((void**)&gx, g_gx);
    float* wcomb;  cudaGetSymbolAddress((void**)&wcomb, g_wcomb);
    float* gbias;  cudaGetSymbolAddress((void**)&gbias, g_gbias);

    cudaStream_t s1;
    cudaStreamCreateWithFlags(&s1, cudaStreamNonBlocking);
    cudaEvent_t evFork, evS1, evPrep, evEmb;
    cudaEventCreateWithFlags(&evFork, cudaEventDisableTiming);
    cudaEventCreateWithFlags(&evS1, cudaEventDisableTiming);
    cudaEventCreateWithFlags(&evPrep, cudaEventDisableTiming);
    cudaEventCreateWithFlags(&evEmb, cudaEventDisableTiming);

    // ---- fork: side branch (independent of the big key GEMM) ----
    cudaEventRecord(evFork, 0);
    cudaStreamWaitEvent(s1, evFork, 0);
    gemm_dual<<<dim3(4, 4, 2), 256, SM2, s1>>>(
        embedding, W_fc1, pre10, b_fc1, 1024,
        type_mask, W_func, funcb, b_func, DTY);
    k_side<<<384, 256, 0, s1>>>(W_fc1, W_emb, b_emb, W_fc2, b_fc2, W_ih, b_ih, b_hh);
    cudaEventRecord(evS1, s1);

    // ---- main stream: key GEMM -> prep ----
    gemm_k<8, 1, 128, true>
        <<<dim3(BB * NN / 128, 1), 256, SMB>>>(ent, W_key, padkey, b_key, 256, 32);
    k_prep<<<BB, 32>>>(avail, selected, endv);
    cudaEventRecord(evPrep, 0);

    // ---- k_emb only needs g_prefix: run on side stream ----
    cudaStreamWaitEvent(s1, evPrep, 0);
    k_emb<<<BB, 256, 0, s1>>>(out, embedding, W_emb, b_emb);
    cudaEventRecord(evEmb, s1);

    // ---- main chain continues after side precomputes land ----
    cudaStreamWaitEvent(0, evS1, 0);
    k_gA<<<BB, 256>>>();
    gemm_g<8, 1, 128>
        <<<dim3(BB * TT / 128, 4), 256, SMB>>>(relua, wcomb, gx, gbias, 256, 128);
    k_lstm<<<BB, 128>>>(W_hh);
    k_logits<<<dim3(5, BB), 256>>>(out);

    // ---- join ----
    cudaStreamWaitEvent(0, evEmb, 0);
}